// round 8
// baseline (speedup 1.0000x reference)
#include <cuda_runtime.h>
#include <cuda_bf16.h>
#include <math.h>
#include <stdint.h>

#define BB 8
#define NN 1024
#define SS 1024
#define CC 768
#define HH 12
#define DD 64
#define SCALEF 0.125f

#define LDT 72        // bf16 elems per 64-wide tile row (144B, conflict-free)
#define LDR 66        // fp32 reduction row stride
#define NT 512
#define TILEB (128 * LDT * 2)   // 18432 B per 128x64 bf16 tile

// -------- scratch (device globals; no allocation allowed) --------
__device__ __align__(256) __nv_bfloat16 g_xq_h[(size_t)BB * NN * CC];
__device__ __align__(256) __nv_bfloat16 g_xq_l[(size_t)BB * NN * CC];
__device__ __align__(256) __nv_bfloat16 g_xk_h[(size_t)BB * SS * CC];
__device__ __align__(256) __nv_bfloat16 g_xk_l[(size_t)BB * SS * CC];
__device__ __align__(256) __nv_bfloat16 g_xv_h[(size_t)BB * SS * CC];
__device__ __align__(256) __nv_bfloat16 g_xv_l[(size_t)BB * SS * CC];
__device__ __align__(256) __nv_bfloat16 g_wq_h[(size_t)CC * CC];
__device__ __align__(256) __nv_bfloat16 g_wq_l[(size_t)CC * CC];
__device__ __align__(256) __nv_bfloat16 g_wk_h[(size_t)CC * CC];
__device__ __align__(256) __nv_bfloat16 g_wk_l[(size_t)CC * CC];
__device__ __align__(256) __nv_bfloat16 g_wv_h[(size_t)CC * CC];
__device__ __align__(256) __nv_bfloat16 g_wv_l[(size_t)CC * CC];
__device__ __align__(256) __nv_bfloat16 g_wo_h[(size_t)CC * CC];
__device__ __align__(256) __nv_bfloat16 g_wo_l[(size_t)CC * CC];
__device__ __align__(256) __nv_bfloat16 g_Qh[(size_t)BB * HH * NN * DD];
__device__ __align__(256) __nv_bfloat16 g_Ql[(size_t)BB * HH * NN * DD];
__device__ __align__(256) __nv_bfloat16 g_Kh[(size_t)BB * HH * SS * DD];
__device__ __align__(256) __nv_bfloat16 g_Kl[(size_t)BB * HH * SS * DD];
__device__ __align__(256) __nv_bfloat16 g_Vh[(size_t)BB * HH * SS * DD];
__device__ __align__(256) __nv_bfloat16 g_Vl[(size_t)BB * HH * SS * DD];
__device__ __align__(256) __nv_bfloat16 g_AOh[(size_t)BB * NN * CC];
__device__ __align__(256) __nv_bfloat16 g_AOl[(size_t)BB * NN * CC];
__device__ float g_lse[BB * HH * NN];
__device__ float g_isu[BB * HH * NN];

// ============================================================================
// helpers
// ============================================================================
__device__ __forceinline__ uint32_t smem_u32(const void* p) {
    uint32_t a;
    asm("{ .reg .u64 t; cvta.to.shared.u64 t, %1; cvt.u32.u64 %0, t; }" : "=r"(a) : "l"(p));
    return a;
}
__device__ __forceinline__ void mma_bf16(float* c, const uint32_t* a, const uint32_t* b) {
    asm volatile("mma.sync.aligned.m16n8k16.row.col.f32.bf16.bf16.f32 "
        "{%0,%1,%2,%3}, {%4,%5,%6,%7}, {%8,%9}, {%0,%1,%2,%3};"
        : "+f"(c[0]), "+f"(c[1]), "+f"(c[2]), "+f"(c[3])
        : "r"(a[0]), "r"(a[1]), "r"(a[2]), "r"(a[3]), "r"(b[0]), "r"(b[1]));
}
__device__ __forceinline__ void ldsm_x4(uint32_t* r, uint32_t a) {
    asm volatile("ldmatrix.sync.aligned.m8n8.x4.shared.b16 {%0,%1,%2,%3}, [%4];"
        : "=r"(r[0]), "=r"(r[1]), "=r"(r[2]), "=r"(r[3]) : "r"(a));
}
__device__ __forceinline__ void ldsm_x4t(uint32_t* r, uint32_t a) {
    asm volatile("ldmatrix.sync.aligned.m8n8.x4.trans.shared.b16 {%0,%1,%2,%3}, [%4];"
        : "=r"(r[0]), "=r"(r[1]), "=r"(r[2]), "=r"(r[3]) : "r"(a));
}
#define CPA16(dst, src) \
    asm volatile("cp.async.cg.shared.global [%0], [%1], 16;" :: "r"(dst), "l"(src) : "memory")
#define CPA_COMMIT() asm volatile("cp.async.commit_group;" ::: "memory")
#define CPA_WAIT(n)  asm volatile("cp.async.wait_group %0;" :: "n"(n) : "memory")

// FMA-pipe exp: rel err ~2e-7, no MUFU.
__device__ __forceinline__ float fexp(float x) {
    float t = x * 1.4426950408889634f;
    t = fmaxf(t, -120.0f);
    int ii = __float2int_rn(t);
    float fi = (float)ii;
    float g = fmaf(-fi, 0.6931471824645996f, x);      // ln2_hi
    g = fmaf(-fi, -1.904654323148236e-09f, g);        // ln2_lo
    float p = fmaf(g, 1.3888889e-3f, 8.3333333e-3f);
    p = fmaf(g, p, 4.1666668e-2f);
    p = fmaf(g, p, 1.6666667e-1f);
    p = fmaf(g, p, 0.5f);
    p = fmaf(g, p, 1.0f);
    p = fmaf(g, p, 1.0f);
    return __int_as_float((ii + 127) << 23) * p;
}
__device__ __forceinline__ uint32_t packbf(float x, float y) {
    __nv_bfloat162 t = __halves2bfloat162(__float2bfloat16(x), __float2bfloat16(y));
    return *(uint32_t*)&t;
}
__device__ __forceinline__ float bflo(float x) {
    return x - __bfloat162float(__float2bfloat16(x));
}

// ============================================================================
// fp32 -> bf16 hi/lo split (streaming)
// ============================================================================
__global__ void split_bf16(const float* __restrict__ x, __nv_bfloat16* __restrict__ hi,
                           __nv_bfloat16* __restrict__ lo, int n4) {
    int i = blockIdx.x * blockDim.x + threadIdx.x;
    if (i >= n4) return;
    float4 v = *(const float4*)(x + (size_t)i * 4);
    __nv_bfloat16 h0 = __float2bfloat16(v.x), h1 = __float2bfloat16(v.y);
    __nv_bfloat16 h2 = __float2bfloat16(v.z), h3 = __float2bfloat16(v.w);
    *(__nv_bfloat162*)(hi + (size_t)i * 4)     = __halves2bfloat162(h0, h1);
    *(__nv_bfloat162*)(hi + (size_t)i * 4 + 2) = __halves2bfloat162(h2, h3);
    *(__nv_bfloat162*)(lo + (size_t)i * 4)     = __halves2bfloat162(
        __float2bfloat16(v.x - __bfloat162float(h0)), __float2bfloat16(v.y - __bfloat162float(h1)));
    *(__nv_bfloat162*)(lo + (size_t)i * 4 + 2) = __halves2bfloat162(
        __float2bfloat16(v.z - __bfloat162float(h2)), __float2bfloat16(v.w - __bfloat162float(h3)));
}

// ============================================================================
// shared GEMM mainloop: c[2][4][4] += X[128xCC] . W[128xCC]^T tile (3-term)
// ============================================================================
__device__ __forceinline__ void gemm_mainloop(
    const __nv_bfloat16* __restrict__ Xh, const __nv_bfloat16* __restrict__ Xl,
    const __nv_bfloat16* __restrict__ Wh, const __nv_bfloat16* __restrict__ Wl,
    int m0, int n0, uint32_t s0, int tid, int lane, int wm, int wn,
    float c[2][4][4]) {
    auto issue = [&](int ch, int buf) {
        const size_t xb = (size_t)m0 * CC + ch * 64;
        const size_t wb = (size_t)n0 * CC + ch * 64;
        const uint32_t base = s0 + buf * 4 * TILEB;
        #pragma unroll
        for (int t = 0; t < 2; t++) {
            const int id = tid + NT * t, row = id >> 3, seg = id & 7;
            const uint32_t doff = (uint32_t)(row * LDT + seg * 8) * 2;
            const size_t sx = xb + (size_t)row * CC + seg * 8;
            const size_t sw = wb + (size_t)row * CC + seg * 8;
            CPA16(base + 0 * TILEB + doff, Xh + sx);
            CPA16(base + 1 * TILEB + doff, Xl + sx);
            CPA16(base + 2 * TILEB + doff, Wh + sw);
            CPA16(base + 3 * TILEB + doff, Wl + sw);
        }
    };
    issue(0, 0); CPA_COMMIT(); CPA_WAIT(0);
    __syncthreads();
    int buf = 0;
    for (int ch = 0; ch < 12; ch++) {
        if (ch < 11) { issue(ch + 1, buf ^ 1); CPA_COMMIT(); }
        const uint32_t aH = s0 + buf * 4 * TILEB, aL = aH + TILEB;
        const uint32_t bH = aL + TILEB, bL = bH + TILEB;
        #pragma unroll
        for (int ks = 0; ks < 4; ks++) {
            uint32_t ah[2][4], al[2][4];
            #pragma unroll
            for (int mi = 0; mi < 2; mi++) {
                uint32_t off = ((wm * 32 + mi * 16 + (lane & 15)) * LDT + ks * 16 + (lane >> 4) * 8) * 2;
                ldsm_x4(ah[mi], aH + off);
                ldsm_x4(al[mi], aL + off);
            }
            #pragma unroll
            for (int nip = 0; nip < 2; nip++) {
                uint32_t off = ((wn * 32 + nip * 16 + (lane >> 4) * 8 + (lane & 7)) * LDT
                                + ks * 16 + ((lane >> 3) & 1) * 8) * 2;
                uint32_t th[4], tl[4];
                ldsm_x4(th, bH + off);
                ldsm_x4(tl, bL + off);
                uint32_t b0[2] = {th[0], th[1]}, b1[2] = {th[2], th[3]};
                uint32_t e0[2] = {tl[0], tl[1]}, e1[2] = {tl[2], tl[3]};
                #pragma unroll
                for (int mi = 0; mi < 2; mi++) {
                    mma_bf16(c[mi][nip * 2],     ah[mi], b0);
                    mma_bf16(c[mi][nip * 2],     ah[mi], e0);
                    mma_bf16(c[mi][nip * 2],     al[mi], b0);
                    mma_bf16(c[mi][nip * 2 + 1], ah[mi], b1);
                    mma_bf16(c[mi][nip * 2 + 1], ah[mi], e1);
                    mma_bf16(c[mi][nip * 2 + 1], al[mi], b1);
                }
            }
        }
        CPA_WAIT(0);
        __syncthreads();
        buf ^= 1;
    }
}

// QKV projections, grid.z selects which
__global__ void __launch_bounds__(NT, 1) tc_gemm_qkv() {
    extern __shared__ char sm[];
    const uint32_t s0 = smem_u32(sm);
    const int tid = threadIdx.x, lane = tid & 31, wid = tid >> 5;
    const int wm = wid & 3, wn = wid >> 2;
    const int m0 = blockIdx.y * 128, n0 = blockIdx.x * 128, z = blockIdx.z;
    const __nv_bfloat16 *Xh, *Xl, *Wh, *Wl;
    __nv_bfloat16 *Yh, *Yl;
    if (z == 0)      { Xh = g_xq_h; Xl = g_xq_l; Wh = g_wq_h; Wl = g_wq_l; Yh = g_Qh; Yl = g_Ql; }
    else if (z == 1) { Xh = g_xk_h; Xl = g_xk_l; Wh = g_wk_h; Wl = g_wk_l; Yh = g_Kh; Yl = g_Kl; }
    else             { Xh = g_xv_h; Xl = g_xv_l; Wh = g_wv_h; Wl = g_wv_l; Yh = g_Vh; Yl = g_Vl; }

    float c[2][4][4] = {};
    gemm_mainloop(Xh, Xl, Wh, Wl, m0, n0, s0, tid, lane, wm, wn, c);

    const int qr = lane >> 2, qc = (lane & 3) * 2;
    #pragma unroll
    for (int mi = 0; mi < 2; mi++)
        #pragma unroll
        for (int ni = 0; ni < 4; ni++) {
            const int rowg = m0 + wm * 32 + mi * 16 + qr;
            const int b = rowg >> 10, r = rowg & 1023;
            const int col = n0 + wn * 32 + ni * 8 + qc;
            const int h = col >> 6, d = col & 63;
            const size_t o0 = ((size_t)(b * HH + h) * NN + r) * DD + d;
            const size_t o1 = o0 + (size_t)8 * DD;
            float x0 = c[mi][ni][0], x1 = c[mi][ni][1];
            float x2 = c[mi][ni][2], x3 = c[mi][ni][3];
            *(uint32_t*)(Yh + o0) = packbf(x0, x1);
            *(uint32_t*)(Yh + o1) = packbf(x2, x3);
            *(uint32_t*)(Yl + o0) = packbf(bflo(x0), bflo(x1));
            *(uint32_t*)(Yl + o1) = packbf(bflo(x2), bflo(x3));
        }
}

// output projection: AO @ Wo + bo -> fp32
__global__ void __launch_bounds__(NT, 1) tc_gemm_out(const float* __restrict__ bias,
                                                     float* __restrict__ Yf) {
    extern __shared__ char sm[];
    const uint32_t s0 = smem_u32(sm);
    const int tid = threadIdx.x, lane = tid & 31, wid = tid >> 5;
    const int wm = wid & 3, wn = wid >> 2;
    const int m0 = blockIdx.y * 128, n0 = blockIdx.x * 128;

    float c[2][4][4] = {};
    gemm_mainloop(g_AOh, g_AOl, g_wo_h, g_wo_l, m0, n0, s0, tid, lane, wm, wn, c);

    const int qr = lane >> 2, qc = (lane & 3) * 2;
    #pragma unroll
    for (int mi = 0; mi < 2; mi++)
        #pragma unroll
        for (int ni = 0; ni < 4; ni++) {
            const int row = m0 + wm * 32 + mi * 16 + qr;
            const int col = n0 + wn * 32 + ni * 8 + qc;
            *(float2*)(Yf + (size_t)row * CC + col) =
                make_float2(c[mi][ni][0] + bias[col], c[mi][ni][1] + bias[col + 1]);
            *(float2*)(Yf + (size_t)(row + 8) * CC + col) =
                make_float2(c[mi][ni][2] + bias[col], c[mi][ni][3] + bias[col + 1]);
        }
}

// copy a head-major 128x64 bf16 tile pair (hi,lo) to smem via cp.async
__device__ __forceinline__ void cpa_tile_pair(uint32_t dhi, uint32_t dlo,
                                              const __nv_bfloat16* __restrict__ shi,
                                              const __nv_bfloat16* __restrict__ slo,
                                              size_t base, int tid) {
    #pragma unroll
    for (int t = 0; t < 2; t++) {
        const int id = tid + NT * t, row = id >> 3, seg = id & 7;
        const uint32_t doff = (uint32_t)(row * LDT + seg * 8) * 2;
        const size_t s = base + (size_t)row * 64 + seg * 8;
        CPA16(dhi + doff, shi + s);
        CPA16(dlo + doff, slo + s);
    }
}

// ============================================================================
// Pass 1: per-row ssum = sum exp(scores), usum = sum exp(scores + aw).
// 4x4 warps, 128 q-rows x 8 s-chunks. fexp on FMA pipe.
// ============================================================================
__global__ void __launch_bounds__(NT, 1) attn_stats(const float* __restrict__ AW) {
    extern __shared__ char sm[];
    const uint32_t s0 = smem_u32(sm);
    const uint32_t sQH = s0, sQL = s0 + TILEB;
    float* redS = (float*)(sm + 6 * TILEB);
    float* redU = redS + 4 * 128;

    const int tid = threadIdx.x, lane = tid & 31, wid = tid >> 5;
    const int wm = wid & 3, wn = wid >> 2;
    const int bh = blockIdx.y;
    const int q0 = blockIdx.x * 128;
    const int qr = lane >> 2, qc = (lane & 3) * 2;

    const size_t qbase = ((size_t)bh * NN + q0) * DD;
    const size_t kbase0 = (size_t)bh * SS * DD;

    cpa_tile_pair(sQH, sQL, g_Qh, g_Ql, qbase, tid);
    cpa_tile_pair(s0 + 2 * TILEB, s0 + 3 * TILEB, g_Kh, g_Kl, kbase0, tid);
    CPA_COMMIT(); CPA_WAIT(0);
    __syncthreads();

    float ssum[4] = {}, usum[4] = {};

    for (int sc = 0; sc < 8; sc++) {
        const int buf = sc & 1;
        if (sc < 7) {
            cpa_tile_pair(s0 + (2 + 2 * (buf ^ 1)) * TILEB, s0 + (3 + 2 * (buf ^ 1)) * TILEB,
                          g_Kh, g_Kl, kbase0 + (size_t)(sc + 1) * 128 * DD, tid);
            CPA_COMMIT();
        }
        const uint32_t kH = s0 + (2 + 2 * buf) * TILEB, kL = kH + TILEB;

        float c[2][4][4] = {};
        #pragma unroll
        for (int ks = 0; ks < 4; ks++) {
            uint32_t ah[2][4], al[2][4];
            #pragma unroll
            for (int mi = 0; mi < 2; mi++) {
                uint32_t off = ((wm * 32 + mi * 16 + (lane & 15)) * LDT + ks * 16 + (lane >> 4) * 8) * 2;
                ldsm_x4(ah[mi], sQH + off);
                ldsm_x4(al[mi], sQL + off);
            }
            #pragma unroll
            for (int nip = 0; nip < 2; nip++) {
                uint32_t off = ((wn * 32 + nip * 16 + (lane >> 4) * 8 + (lane & 7)) * LDT
                                + ks * 16 + ((lane >> 3) & 1) * 8) * 2;
                uint32_t th[4], tl[4];
                ldsm_x4(th, kH + off);
                ldsm_x4(tl, kL + off);
                uint32_t b0[2] = {th[0], th[1]}, b1[2] = {th[2], th[3]};
                uint32_t e0[2] = {tl[0], tl[1]}, e1[2] = {tl[2], tl[3]};
                #pragma unroll
                for (int mi = 0; mi < 2; mi++) {
                    mma_bf16(c[mi][nip * 2],     ah[mi], b0);
                    mma_bf16(c[mi][nip * 2],     ah[mi], e0);
                    mma_bf16(c[mi][nip * 2],     al[mi], b0);
                    mma_bf16(c[mi][nip * 2 + 1], ah[mi], b1);
                    mma_bf16(c[mi][nip * 2 + 1], ah[mi], e1);
                    mma_bf16(c[mi][nip * 2 + 1], al[mi], b1);
                }
            }
        }

        const int s0c = sc * 128;
        #pragma unroll
        for (int mi = 0; mi < 2; mi++) {
            const size_t rb = ((size_t)bh * NN + q0 + wm * 32 + mi * 16 + qr) * SS + s0c + wn * 32 + qc;
            #pragma unroll
            for (int ni = 0; ni < 4; ni++) {
                float2 aw0 = *(const float2*)(AW + rb + ni * 8);
                float2 aw1 = *(const float2*)(AW + rb + (size_t)8 * SS + ni * 8);
                float sc00 = c[mi][ni][0] * SCALEF, sc01 = c[mi][ni][1] * SCALEF;
                float sc10 = c[mi][ni][2] * SCALEF, sc11 = c[mi][ni][3] * SCALEF;
                ssum[mi * 2]     += fexp(sc00) + fexp(sc01);
                ssum[mi * 2 + 1] += fexp(sc10) + fexp(sc11);
                usum[mi * 2]     += fexp(sc00 + aw0.x) + fexp(sc01 + aw0.y);
                usum[mi * 2 + 1] += fexp(sc10 + aw1.x) + fexp(sc11 + aw1.y);
            }
        }
        CPA_WAIT(0);
        __syncthreads();
    }

    #pragma unroll
    for (int sl = 0; sl < 4; sl++) {
        ssum[sl] += __shfl_xor_sync(~0u, ssum[sl], 1);
        ssum[sl] += __shfl_xor_sync(~0u, ssum[sl], 2);
        usum[sl] += __shfl_xor_sync(~0u, usum[sl], 1);
        usum[sl] += __shfl_xor_sync(~0u, usum[sl], 2);
    }
    if ((lane & 3) == 0) {
        #pragma unroll
        for (int sl = 0; sl < 4; sl++) {
            const int row = wm * 32 + (sl >> 1) * 16 + qr + 8 * (sl & 1);
            redS[wn * 128 + row] = ssum[sl];
            redU[wn * 128 + row] = usum[sl];
        }
    }
    __syncthreads();
    if (tid < 128) {
        float st = redS[tid] + redS[128 + tid] + redS[256 + tid] + redS[384 + tid];
        float ut = redU[tid] + redU[128 + tid] + redU[256 + tid] + redU[384 + tid];
        const int gi = bh * NN + q0 + tid;
        g_lse[gi] = __logf(st);
        g_isu[gi] = 1.0f / ut;
    }
}

// ============================================================================
// Pass 2: warps 8(m)x2(s). QK C-fragments become PV A-fragments in registers
// (no P smem). Partial O reduced across the 2 wn-groups at the end.
// smem: Q(2) + K dbuf(4) + V dbuf(4) = 10 TILEB = 184320 B.
// ============================================================================
__global__ void __launch_bounds__(NT, 1) attn_av(const float* __restrict__ AW,
                                                 float* __restrict__ LOGOUT) {
    extern __shared__ char sm[];
    const uint32_t s0 = smem_u32(sm);
    const uint32_t sQH = s0, sQL = s0 + TILEB;

    const int tid = threadIdx.x, lane = tid & 31, wid = tid >> 5;
    const int wm = wid & 7, wn = wid >> 3;
    const int bh = blockIdx.y;
    const int q0 = blockIdx.x * 128;
    const int qr = lane >> 2, qc = (lane & 3) * 2;

    const size_t qbase = ((size_t)bh * NN + q0) * DD;
    const size_t kvbase = (size_t)bh * SS * DD;

    cpa_tile_pair(sQH, sQL, g_Qh, g_Ql, qbase, tid);
    cpa_tile_pair(s0 + 2 * TILEB, s0 + 3 * TILEB, g_Kh, g_Kl, kvbase, tid);
    cpa_tile_pair(s0 + 6 * TILEB, s0 + 7 * TILEB, g_Vh, g_Vl, kvbase, tid);
    CPA_COMMIT(); CPA_WAIT(0);
    __syncthreads();

    const float lse0 = g_lse[bh * NN + q0 + wm * 16 + qr];
    const float lse1 = g_lse[bh * NN + q0 + wm * 16 + qr + 8];
    const float isu0 = g_isu[bh * NN + q0 + wm * 16 + qr];
    const float isu1 = g_isu[bh * NN + q0 + wm * 16 + qr + 8];

    float c2[8][4] = {};

    for (int sc = 0; sc < 8; sc++) {
        const int buf = sc & 1;
        if (sc < 7) {
            cpa_tile_pair(s0 + (2 + 2 * (buf ^ 1)) * TILEB, s0 + (3 + 2 * (buf ^ 1)) * TILEB,
                          g_Kh, g_Kl, kvbase + (size_t)(sc + 1) * 128 * DD, tid);
            cpa_tile_pair(s0 + (6 + 2 * (buf ^ 1)) * TILEB, s0 + (7 + 2 * (buf ^ 1)) * TILEB,
                          g_Vh, g_Vl, kvbase + (size_t)(sc + 1) * 128 * DD, tid);
            CPA_COMMIT();
        }
        const uint32_t kH = s0 + (2 + 2 * buf) * TILEB, kL = kH + TILEB;
        const uint32_t vH = s0 + (6 + 2 * buf) * TILEB, vL = vH + TILEB;

        // ---- QK: c[ni][...] over rows wm*16+{qr,qr+8}, s = wn*64+ni*8+{qc,qc+1}
        float c[8][4] = {};
        #pragma unroll
        for (int ks = 0; ks < 4; ks++) {
            uint32_t ah[4], al[4];
            const uint32_t aoff = ((wm * 16 + (lane & 15)) * LDT + ks * 16 + (lane >> 4) * 8) * 2;
            ldsm_x4(ah, sQH + aoff);
            ldsm_x4(al, sQL + aoff);
            #pragma unroll
            for (int nip = 0; nip < 4; nip++) {
                uint32_t off = ((wn * 64 + nip * 16 + (lane >> 4) * 8 + (lane & 7)) * LDT
                                + ks * 16 + ((lane >> 3) & 1) * 8) * 2;
                uint32_t th[4], tl[4];
                ldsm_x4(th, kH + off);
                ldsm_x4(tl, kL + off);
                uint32_t b0[2] = {th[0], th[1]}, b1[2] = {th[2], th[3]};
                uint32_t e0[2] = {tl[0], tl[1]}, e1[2] = {tl[2], tl[3]};
                mma_bf16(c[nip * 2],     ah, b0);
                mma_bf16(c[nip * 2],     ah, e0);
                mma_bf16(c[nip * 2],     al, b0);
                mma_bf16(c[nip * 2 + 1], ah, b1);
                mma_bf16(c[nip * 2 + 1], ah, e1);
                mma_bf16(c[nip * 2 + 1], al, b1);
            }
        }

        // ---- softmax + logits; overwrite c with p (fp32)
        const size_t rb0 = ((size_t)bh * NN + q0 + wm * 16 + qr) * SS + sc * 128 + wn * 64 + qc;
        #pragma unroll
        for (int ni = 0; ni < 8; ni++) {
            const size_t rb = rb0 + ni * 8;
            float2 aw0 = *(const float2*)(AW + rb);
            float2 aw1 = *(const float2*)(AW + rb + (size_t)8 * SS);
            float u00 = fmaf(c[ni][0], SCALEF, aw0.x);
            float u01 = fmaf(c[ni][1], SCALEF, aw0.y);
            float u10 = fmaf(c[ni][2], SCALEF, aw1.x);
            float u11 = fmaf(c[ni][3], SCALEF, aw1.y);
            *(float2*)(LOGOUT + rb) = make_float2(u00 - lse0, u01 - lse0);
            *(float2*)(LOGOUT + rb + (size_t)8 * SS) = make_float2(u10 - lse1, u11 - lse1);
            c[ni][0] = fexp(u00) * isu0;
            c[ni][1] = fexp(u01) * isu0;
            c[ni][2] = fexp(u10) * isu1;
            c[ni][3] = fexp(u11) * isu1;
        }

        // ---- PV from register P: k-slice wn*64 + ks2*16, A-frags from c
        #pragma unroll
        for (int ks2 = 0; ks2 < 4; ks2++) {
            const int n2 = ks2 * 2;
            uint32_t ph[4], pl[4];
            ph[0] = packbf(c[n2][0], c[n2][1]);
            ph[1] = packbf(c[n2][2], c[n2][3]);
            ph[2] = packbf(c[n2 + 1][0], c[n2 + 1][1]);
            ph[3] = packbf(c[n2 + 1][2], c[n2 + 1][3]);
            pl[0] = packbf(bflo(c[n2][0]), bflo(c[n2][1]));
            pl[1] = packbf(bflo(c[n2][2]), bflo(c[n2][3]));
            pl[2] = packbf(bflo(c[n2 + 1][0]), bflo(c[n2 + 1][1]));
            pl[3] = packbf(bflo(c[n2 + 1][2]), bflo(c[n2 + 1][3]));
            #pragma unroll
            for (int njp = 0; njp < 4; njp++) {
                uint32_t off = ((wn * 64 + ks2 * 16 + (lane & 15)) * LDT
                                + (njp * 2 + (lane >> 4)) * 8) * 2;
                uint32_t th[4], tl[4];
                ldsm_x4t(th, vH + off);
                ldsm_x4t(tl, vL + off);
                uint32_t b0[2] = {th[0], th[1]}, b1[2] = {th[2], th[3]};
                uint32_t e0[2] = {tl[0], tl[1]}, e1[2] = {tl[2], tl[3]};
                mma_bf16(c2[njp * 2],     ph, b0);
                mma_bf16(c2[njp * 2],     ph, e0);
                mma_bf16(c2[njp * 2],     pl, b0);
                mma_bf16(c2[njp * 2 + 1], ph, b1);
                mma_bf16(c2[njp * 2 + 1], ph, e1);
                mma_bf16(c2[njp * 2 + 1], pl, b1);
            }
        }
        CPA_WAIT(0);
        __syncthreads();
    }

    // ---- reduce partial O across wn groups, then epilogue (pre-split AO)
    float* red = (float*)(sm + 2 * TILEB);
    if (wn == 1) {
        #pragma unroll
        for (int nj = 0; nj < 8; nj++) {
            red[(wm * 16 + qr) * LDR + nj * 8 + qc]         = c2[nj][0];
            red[(wm * 16 + qr) * LDR + nj * 8 + qc + 1]     = c2[nj][1];
            red[(wm * 16 + qr + 8) * LDR + nj * 8 + qc]     = c2[nj][2];
            red[(wm * 16 + qr + 8) * LDR + nj * 8 + qc + 1] = c2[nj][3];
        }
    }
    __syncthreads();
    if (wn == 0) {
        const int b = bh / HH, h = bh % HH;
        #pragma unroll
        for (int nj = 0; nj < 8; nj++) {
            float x0 = c2[nj][0] + red[(wm * 16 + qr) * LDR + nj * 8 + qc];
            float x1 = c2[nj][1] + red[(wm * 16 + qr) * LDR + nj * 8 + qc + 1];
            float x2 = c2[nj][2] + red[(wm * 16 + qr + 8) * LDR + nj * 8 + qc];
            float x3 = c2[nj][3] + red[(wm * 16 + qr + 8) * LDR + nj * 8 + qc + 1];
            const int col = h * DD + nj * 8 + qc;
            const size_t o0 = (size_t)(b * NN + q0 + wm * 16 + qr) * CC + col;
            const size_t o1 = (size_t)(b * NN + q0 + wm * 16 + qr + 8) * CC + col;
            *(uint32_t*)(g_AOh + o0) = packbf(x0, x1);
            *(uint32_t*)(g_AOh + o1) = packbf(x2, x3);
            *(uint32_t*)(g_AOl + o0) = packbf(bflo(x0), bflo(x1));
            *(uint32_t*)(g_AOl + o1) = packbf(bflo(x2), bflo(x3));
        }
    }
}

// ============================================================================
extern "C" void kernel_launch(void* const* d_in, const int* in_sizes, int n_in,
                              void* d_out, int out_size) {
    const float* query = (const float*)d_in[0];
    const float* key_  = (const float*)d_in[1];
    const float* value = (const float*)d_in[2];
    const float* aw    = (const float*)d_in[3];
    const float* Wq    = (const float*)d_in[4];
    const float* Wk    = (const float*)d_in[5];
    const float* Wv    = (const float*)d_in[6];
    const float* Wo    = (const float*)d_in[7];
    const float* bo    = (const float*)d_in[8];

    float* out    = (float*)d_out;                       // [B,N,C]
    float* logout = out + (size_t)BB * NN * CC;          // [B,H,N,S]

    __nv_bfloat16 *xqh, *xql, *xkh, *xkl, *xvh, *xvl;
    __nv_bfloat16 *wqh, *wql, *wkh, *wkl, *wvh, *wvl, *woh, *wol;
    cudaGetSymbolAddress((void**)&xqh, g_xq_h); cudaGetSymbolAddress((void**)&xql, g_xq_l);
    cudaGetSymbolAddress((void**)&xkh, g_xk_h); cudaGetSymbolAddress((void**)&xkl, g_xk_l);
    cudaGetSymbolAddress((void**)&xvh, g_xv_h); cudaGetSymbolAddress((void**)&xvl, g_xv_l);
    cudaGetSymbolAddress((void**)&wqh, g_wq_h); cudaGetSymbolAddress((void**)&wql, g_wq_l);
    cudaGetSymbolAddress((void**)&wkh, g_wk_h); cudaGetSymbolAddress((void**)&wkl, g_wk_l);
    cudaGetSymbolAddress((void**)&wvh, g_wv_h); cudaGetSymbolAddress((void**)&wvl, g_wv_l);
    cudaGetSymbolAddress((void**)&woh, g_wo_h); cudaGetSymbolAddress((void**)&wol, g_wo_l);

    const int smem_gemm  = 8 * TILEB;                    // 147456
    const int smem_stats = 6 * TILEB + 2 * 4 * 128 * 4;  // 114688
    const int smem_av    = 10 * TILEB;                   // 184320
    cudaFuncSetAttribute(tc_gemm_qkv, cudaFuncAttributeMaxDynamicSharedMemorySize, smem_gemm);
    cudaFuncSetAttribute(tc_gemm_out, cudaFuncAttributeMaxDynamicSharedMemorySize, smem_gemm);
    cudaFuncSetAttribute(attn_stats,  cudaFuncAttributeMaxDynamicSharedMemorySize, smem_stats);
    cudaFuncSetAttribute(attn_av,     cudaFuncAttributeMaxDynamicSharedMemorySize, smem_av);

    const int nX4 = (BB * NN * CC) / 4;
    const int nW4 = (CC * CC) / 4;
    dim3 gqkv(CC / 128, (BB * NN) / 128, 3);   // 6 x 64 x 3
    dim3 gp(CC / 128, (BB * NN) / 128);        // 6 x 64
    dim3 ga(NN / 128, BB * HH);                // 8 x 96

    split_bf16<<<(nX4 + 255) / 256, 256>>>(query, xqh, xql, nX4);
    split_bf16<<<(nX4 + 255) / 256, 256>>>(key_,  xkh, xkl, nX4);
    split_bf16<<<(nX4 + 255) / 256, 256>>>(value, xvh, xvl, nX4);
    split_bf16<<<(nW4 + 255) / 256, 256>>>(Wq, wqh, wql, nW4);
    split_bf16<<<(nW4 + 255) / 256, 256>>>(Wk, wkh, wkl, nW4);
    split_bf16<<<(nW4 + 255) / 256, 256>>>(Wv, wvh, wvl, nW4);
    split_bf16<<<(nW4 + 255) / 256, 256>>>(Wo, woh, wol, nW4);

    tc_gemm_qkv<<<gqkv, NT, smem_gemm>>>();
    attn_stats<<<ga, NT, smem_stats>>>(aw);
    attn_av<<<ga, NT, smem_av>>>(aw, logout);
    tc_gemm_out<<<gp, NT, smem_gemm>>>(bo, out);
}

// round 9
// speedup vs baseline: 1.5636x; 1.5636x over previous
#include <cuda_runtime.h>
#include <cuda_bf16.h>
#include <math.h>
#include <stdint.h>

#define BB 8
#define NN 1024
#define SS 1024
#define CC 768
#define HH 12
#define DD 64
#define SCALEF 0.125f

#define LDT 72        // bf16 elems per 64-wide tile row (144B, conflict-free)
#define LDP 136       // bf16 elems per 128-wide P tile row (272B)
#define NT 512
#define TILEB (128 * LDT * 2)   // 18432 B per 128x64 bf16 tile
#define PTILEB (128 * LDP * 2)  // 34816 B per 128x128 bf16 tile

// -------- scratch (device globals; no allocation allowed) --------
__device__ __align__(256) __nv_bfloat16 g_xq_h[(size_t)BB * NN * CC];
__device__ __align__(256) __nv_bfloat16 g_xq_l[(size_t)BB * NN * CC];
__device__ __align__(256) __nv_bfloat16 g_xk_h[(size_t)BB * SS * CC];
__device__ __align__(256) __nv_bfloat16 g_xk_l[(size_t)BB * SS * CC];
__device__ __align__(256) __nv_bfloat16 g_xv_h[(size_t)BB * SS * CC];
__device__ __align__(256) __nv_bfloat16 g_xv_l[(size_t)BB * SS * CC];
__device__ __align__(256) __nv_bfloat16 g_wq_h[(size_t)CC * CC];
__device__ __align__(256) __nv_bfloat16 g_wq_l[(size_t)CC * CC];
__device__ __align__(256) __nv_bfloat16 g_wk_h[(size_t)CC * CC];
__device__ __align__(256) __nv_bfloat16 g_wk_l[(size_t)CC * CC];
__device__ __align__(256) __nv_bfloat16 g_wv_h[(size_t)CC * CC];
__device__ __align__(256) __nv_bfloat16 g_wv_l[(size_t)CC * CC];
__device__ __align__(256) __nv_bfloat16 g_wo_h[(size_t)CC * CC];
__device__ __align__(256) __nv_bfloat16 g_wo_l[(size_t)CC * CC];
__device__ __align__(256) __nv_bfloat16 g_Qh[(size_t)BB * HH * NN * DD];
__device__ __align__(256) __nv_bfloat16 g_Ql[(size_t)BB * HH * NN * DD];
__device__ __align__(256) __nv_bfloat16 g_Kh[(size_t)BB * HH * SS * DD];
__device__ __align__(256) __nv_bfloat16 g_Kl[(size_t)BB * HH * SS * DD];
__device__ __align__(256) __nv_bfloat16 g_Vh[(size_t)BB * HH * SS * DD];
__device__ __align__(256) __nv_bfloat16 g_Vl[(size_t)BB * HH * SS * DD];
__device__ __align__(256) __nv_bfloat16 g_AOh[(size_t)BB * NN * CC];
__device__ __align__(256) __nv_bfloat16 g_AOl[(size_t)BB * NN * CC];
__device__ float g_lse[BB * HH * NN];
__device__ float g_isu[BB * HH * NN];

// ============================================================================
// helpers
// ============================================================================
__device__ __forceinline__ uint32_t smem_u32(const void* p) {
    uint32_t a;
    asm("{ .reg .u64 t; cvta.to.shared.u64 t, %1; cvt.u32.u64 %0, t; }" : "=r"(a) : "l"(p));
    return a;
}
__device__ __forceinline__ void mma_bf16(float* c, const uint32_t* a, const uint32_t* b) {
    asm volatile("mma.sync.aligned.m16n8k16.row.col.f32.bf16.bf16.f32 "
        "{%0,%1,%2,%3}, {%4,%5,%6,%7}, {%8,%9}, {%0,%1,%2,%3};"
        : "+f"(c[0]), "+f"(c[1]), "+f"(c[2]), "+f"(c[3])
        : "r"(a[0]), "r"(a[1]), "r"(a[2]), "r"(a[3]), "r"(b[0]), "r"(b[1]));
}
__device__ __forceinline__ void ldsm_x4(uint32_t* r, uint32_t a) {
    asm volatile("ldmatrix.sync.aligned.m8n8.x4.shared.b16 {%0,%1,%2,%3}, [%4];"
        : "=r"(r[0]), "=r"(r[1]), "=r"(r[2]), "=r"(r[3]) : "r"(a));
}
__device__ __forceinline__ void ldsm_x2(uint32_t* r, uint32_t a) {
    asm volatile("ldmatrix.sync.aligned.m8n8.x2.shared.b16 {%0,%1}, [%2];"
        : "=r"(r[0]), "=r"(r[1]) : "r"(a));
}
__device__ __forceinline__ void ldsm_x2t(uint32_t* r, uint32_t a) {
    asm volatile("ldmatrix.sync.aligned.m8n8.x2.trans.shared.b16 {%0,%1}, [%2];"
        : "=r"(r[0]), "=r"(r[1]) : "r"(a));
}
#define CPA16(dst, src) \
    asm volatile("cp.async.cg.shared.global [%0], [%1], 16;" :: "r"(dst), "l"(src) : "memory")
#define CPA_COMMIT() asm volatile("cp.async.commit_group;" ::: "memory")
#define CPA_WAIT(n)  asm volatile("cp.async.wait_group %0;" :: "n"(n) : "memory")

__device__ __forceinline__ uint32_t packbf(float x, float y) {
    __nv_bfloat162 t = __halves2bfloat162(__float2bfloat16(x), __float2bfloat16(y));
    return *(uint32_t*)&t;
}
__device__ __forceinline__ float bflo(float x) {
    return x - __bfloat162float(__float2bfloat16(x));
}

// ============================================================================
// fp32 -> bf16 hi/lo split; z selects among up to 4 tensors
// ============================================================================
__device__ __forceinline__ void split_one(const float* __restrict__ x,
                                          __nv_bfloat16* __restrict__ hi,
                                          __nv_bfloat16* __restrict__ lo, int i) {
    float4 v = *(const float4*)(x + (size_t)i * 4);
    __nv_bfloat16 h0 = __float2bfloat16(v.x), h1 = __float2bfloat16(v.y);
    __nv_bfloat16 h2 = __float2bfloat16(v.z), h3 = __float2bfloat16(v.w);
    *(__nv_bfloat162*)(hi + (size_t)i * 4)     = __halves2bfloat162(h0, h1);
    *(__nv_bfloat162*)(hi + (size_t)i * 4 + 2) = __halves2bfloat162(h2, h3);
    *(__nv_bfloat162*)(lo + (size_t)i * 4)     = __halves2bfloat162(
        __float2bfloat16(v.x - __bfloat162float(h0)), __float2bfloat16(v.y - __bfloat162float(h1)));
    *(__nv_bfloat162*)(lo + (size_t)i * 4 + 2) = __halves2bfloat162(
        __float2bfloat16(v.z - __bfloat162float(h2)), __float2bfloat16(v.w - __bfloat162float(h3)));
}

__global__ void split_x3(const float* __restrict__ xq, const float* __restrict__ xk,
                         const float* __restrict__ xv, int n4) {
    int i = blockIdx.x * blockDim.x + threadIdx.x;
    if (i >= n4) return;
    if (blockIdx.z == 0)      split_one(xq, g_xq_h, g_xq_l, i);
    else if (blockIdx.z == 1) split_one(xk, g_xk_h, g_xk_l, i);
    else                      split_one(xv, g_xv_h, g_xv_l, i);
}
__global__ void split_w4(const float* __restrict__ wq, const float* __restrict__ wk,
                         const float* __restrict__ wv, const float* __restrict__ wo, int n4) {
    int i = blockIdx.x * blockDim.x + threadIdx.x;
    if (i >= n4) return;
    if (blockIdx.z == 0)      split_one(wq, g_wq_h, g_wq_l, i);
    else if (blockIdx.z == 1) split_one(wk, g_wk_h, g_wk_l, i);
    else if (blockIdx.z == 2) split_one(wv, g_wv_h, g_wv_l, i);
    else                      split_one(wo, g_wo_h, g_wo_l, i);
}

// ============================================================================
// shared GEMM mainloop (R6-verbatim): c[2][4][4] += X . W^T, 3-term split
// ============================================================================
__device__ __forceinline__ void gemm_mainloop(
    const __nv_bfloat16* __restrict__ Xh, const __nv_bfloat16* __restrict__ Xl,
    const __nv_bfloat16* __restrict__ Wh, const __nv_bfloat16* __restrict__ Wl,
    int m0, int n0, uint32_t s0, int tid, int lane, int wm, int wn,
    float c[2][4][4]) {
    auto issue = [&](int ch, int buf) {
        const size_t xb = (size_t)m0 * CC + ch * 64;
        const size_t wb = (size_t)n0 * CC + ch * 64;
        const uint32_t base = s0 + buf * 4 * TILEB;
        #pragma unroll
        for (int t = 0; t < 2; t++) {
            const int id = tid + NT * t, row = id >> 3, seg = id & 7;
            const uint32_t doff = (uint32_t)(row * LDT + seg * 8) * 2;
            const size_t sx = xb + (size_t)row * CC + seg * 8;
            const size_t sw = wb + (size_t)row * CC + seg * 8;
            CPA16(base + 0 * TILEB + doff, Xh + sx);
            CPA16(base + 1 * TILEB + doff, Xl + sx);
            CPA16(base + 2 * TILEB + doff, Wh + sw);
            CPA16(base + 3 * TILEB + doff, Wl + sw);
        }
    };
    issue(0, 0); CPA_COMMIT(); CPA_WAIT(0);
    __syncthreads();
    int buf = 0;
    for (int ch = 0; ch < 12; ch++) {
        if (ch < 11) { issue(ch + 1, buf ^ 1); CPA_COMMIT(); }
        const uint32_t aH = s0 + buf * 4 * TILEB, aL = aH + TILEB;
        const uint32_t bH = aL + TILEB, bL = bH + TILEB;
        #pragma unroll
        for (int ks = 0; ks < 4; ks++) {
            uint32_t ah[2][4], al[2][4], bh[4][2], bl[4][2];
            #pragma unroll
            for (int mi = 0; mi < 2; mi++) {
                uint32_t off = ((wm * 32 + mi * 16 + (lane & 15)) * LDT + ks * 16 + (lane >> 4) * 8) * 2;
                ldsm_x4(ah[mi], aH + off);
                ldsm_x4(al[mi], aL + off);
            }
            #pragma unroll
            for (int ni = 0; ni < 4; ni++) {
                uint32_t off = ((wn * 32 + ni * 8 + (lane & 7)) * LDT + ks * 16 + ((lane >> 3) & 1) * 8) * 2;
                ldsm_x2(bh[ni], bH + off);
                ldsm_x2(bl[ni], bL + off);
            }
            #pragma unroll
            for (int mi = 0; mi < 2; mi++)
                #pragma unroll
                for (int ni = 0; ni < 4; ni++) {
                    mma_bf16(c[mi][ni], ah[mi], bh[ni]);
                    mma_bf16(c[mi][ni], ah[mi], bl[ni]);
                    mma_bf16(c[mi][ni], al[mi], bh[ni]);
                }
        }
        CPA_WAIT(0);
        __syncthreads();
        buf ^= 1;
    }
}

// QKV projections merged: grid.z selects tensor; head-major pre-split output
__global__ void __launch_bounds__(NT, 1) tc_gemm_qkv() {
    extern __shared__ char sm[];
    const uint32_t s0 = smem_u32(sm);
    const int tid = threadIdx.x, lane = tid & 31, wid = tid >> 5;
    const int wm = wid & 3, wn = wid >> 2;
    const int m0 = blockIdx.y * 128, n0 = blockIdx.x * 128, z = blockIdx.z;
    const __nv_bfloat16 *Xh, *Xl, *Wh, *Wl;
    __nv_bfloat16 *Yh, *Yl;
    if (z == 0)      { Xh = g_xq_h; Xl = g_xq_l; Wh = g_wq_h; Wl = g_wq_l; Yh = g_Qh; Yl = g_Ql; }
    else if (z == 1) { Xh = g_xk_h; Xl = g_xk_l; Wh = g_wk_h; Wl = g_wk_l; Yh = g_Kh; Yl = g_Kl; }
    else             { Xh = g_xv_h; Xl = g_xv_l; Wh = g_wv_h; Wl = g_wv_l; Yh = g_Vh; Yl = g_Vl; }

    float c[2][4][4] = {};
    gemm_mainloop(Xh, Xl, Wh, Wl, m0, n0, s0, tid, lane, wm, wn, c);

    const int qr = lane >> 2, qc = (lane & 3) * 2;
    #pragma unroll
    for (int mi = 0; mi < 2; mi++)
        #pragma unroll
        for (int ni = 0; ni < 4; ni++) {
            const int rowg = m0 + wm * 32 + mi * 16 + qr;
            const int b = rowg >> 10, r = rowg & 1023;
            const int col = n0 + wn * 32 + ni * 8 + qc;
            const int h = col >> 6, d = col & 63;
            const size_t o0 = ((size_t)(b * HH + h) * NN + r) * DD + d;
            const size_t o1 = o0 + (size_t)8 * DD;
            float x0 = c[mi][ni][0], x1 = c[mi][ni][1];
            float x2 = c[mi][ni][2], x3 = c[mi][ni][3];
            *(uint32_t*)(Yh + o0) = packbf(x0, x1);
            *(uint32_t*)(Yh + o1) = packbf(x2, x3);
            *(uint32_t*)(Yl + o0) = packbf(bflo(x0), bflo(x1));
            *(uint32_t*)(Yl + o1) = packbf(bflo(x2), bflo(x3));
        }
}

// output projection: AO @ Wo + bo -> fp32
__global__ void __launch_bounds__(NT, 1) tc_gemm_out(const float* __restrict__ bias,
                                                     float* __restrict__ Yf) {
    extern __shared__ char sm[];
    const uint32_t s0 = smem_u32(sm);
    const int tid = threadIdx.x, lane = tid & 31, wid = tid >> 5;
    const int wm = wid & 3, wn = wid >> 2;
    const int m0 = blockIdx.y * 128, n0 = blockIdx.x * 128;

    float c[2][4][4] = {};
    gemm_mainloop(g_AOh, g_AOl, g_wo_h, g_wo_l, m0, n0, s0, tid, lane, wm, wn, c);

    const int qr = lane >> 2, qc = (lane & 3) * 2;
    #pragma unroll
    for (int mi = 0; mi < 2; mi++)
        #pragma unroll
        for (int ni = 0; ni < 4; ni++) {
            const int row = m0 + wm * 32 + mi * 16 + qr;
            const int col = n0 + wn * 32 + ni * 8 + qc;
            *(float2*)(Yf + (size_t)row * CC + col) =
                make_float2(c[mi][ni][0] + bias[col], c[mi][ni][1] + bias[col + 1]);
            *(float2*)(Yf + (size_t)(row + 8) * CC + col) =
                make_float2(c[mi][ni][2] + bias[col], c[mi][ni][3] + bias[col + 1]);
        }
}

// copy a head-major 128x64 bf16 tile pair (hi,lo) to smem via cp.async
__device__ __forceinline__ void cpa_tile_pair(uint32_t dhi, uint32_t dlo,
                                              const __nv_bfloat16* __restrict__ shi,
                                              const __nv_bfloat16* __restrict__ slo,
                                              size_t base, int tid) {
    #pragma unroll
    for (int t = 0; t < 2; t++) {
        const int id = tid + NT * t, row = id >> 3, seg = id & 7;
        const uint32_t doff = (uint32_t)(row * LDT + seg * 8) * 2;
        const size_t s = base + (size_t)row * 64 + seg * 8;
        CPA16(dhi + doff, shi + s);
        CPA16(dlo + doff, slo + s);
    }
}

// ============================================================================
// Pass 1 (R6-verbatim): ssum = sum exp(scores), usum = sum exp(scores + aw).
// ============================================================================
__global__ void __launch_bounds__(NT, 1) attn_stats(const float* __restrict__ AW) {
    extern __shared__ char sm[];
    const uint32_t s0 = smem_u32(sm);
    const uint32_t sQH = s0, sQL = s0 + TILEB;
    float* redS = (float*)(sm + 6 * TILEB);
    float* redU = redS + 4 * 128;

    const int tid = threadIdx.x, lane = tid & 31, wid = tid >> 5;
    const int wm = wid & 3, wn = wid >> 2;
    const int bh = blockIdx.y;
    const int q0 = blockIdx.x * 128;
    const int qr = lane >> 2, qc = (lane & 3) * 2;

    const size_t qbase = ((size_t)bh * NN + q0) * DD;
    const size_t kbase0 = (size_t)bh * SS * DD;

    cpa_tile_pair(sQH, sQL, g_Qh, g_Ql, qbase, tid);
    cpa_tile_pair(s0 + 2 * TILEB, s0 + 3 * TILEB, g_Kh, g_Kl, kbase0, tid);
    CPA_COMMIT(); CPA_WAIT(0);
    __syncthreads();

    float ssum[4] = {}, usum[4] = {};

    for (int sc = 0; sc < 8; sc++) {
        const int buf = sc & 1;
        if (sc < 7) {
            cpa_tile_pair(s0 + (2 + 2 * (buf ^ 1)) * TILEB, s0 + (3 + 2 * (buf ^ 1)) * TILEB,
                          g_Kh, g_Kl, kbase0 + (size_t)(sc + 1) * 128 * DD, tid);
            CPA_COMMIT();
        }
        const uint32_t kH = s0 + (2 + 2 * buf) * TILEB, kL = kH + TILEB;

        float c[2][4][4] = {};
        #pragma unroll
        for (int ks = 0; ks < 4; ks++) {
            uint32_t ah[2][4], al[2][4], bh2[4][2], bl2[4][2];
            #pragma unroll
            for (int mi = 0; mi < 2; mi++) {
                uint32_t off = ((wm * 32 + mi * 16 + (lane & 15)) * LDT + ks * 16 + (lane >> 4) * 8) * 2;
                ldsm_x4(ah[mi], sQH + off);
                ldsm_x4(al[mi], sQL + off);
            }
            #pragma unroll
            for (int ni = 0; ni < 4; ni++) {
                uint32_t off = ((wn * 32 + ni * 8 + (lane & 7)) * LDT + ks * 16 + ((lane >> 3) & 1) * 8) * 2;
                ldsm_x2(bh2[ni], kH + off);
                ldsm_x2(bl2[ni], kL + off);
            }
            #pragma unroll
            for (int mi = 0; mi < 2; mi++)
                #pragma unroll
                for (int ni = 0; ni < 4; ni++) {
                    mma_bf16(c[mi][ni], ah[mi], bh2[ni]);
                    mma_bf16(c[mi][ni], ah[mi], bl2[ni]);
                    mma_bf16(c[mi][ni], al[mi], bh2[ni]);
                }
        }

        const int s0c = sc * 128;
        #pragma unroll
        for (int mi = 0; mi < 2; mi++) {
            const size_t rb = ((size_t)bh * NN + q0 + wm * 32 + mi * 16 + qr) * SS + s0c + wn * 32 + qc;
            #pragma unroll
            for (int ni = 0; ni < 4; ni++) {
                float2 aw0 = *(const float2*)(AW + rb + ni * 8);
                float2 aw1 = *(const float2*)(AW + rb + (size_t)8 * SS + ni * 8);
                float sc00 = c[mi][ni][0] * SCALEF, sc01 = c[mi][ni][1] * SCALEF;
                float sc10 = c[mi][ni][2] * SCALEF, sc11 = c[mi][ni][3] * SCALEF;
                ssum[mi * 2]     += __expf(sc00) + __expf(sc01);
                ssum[mi * 2 + 1] += __expf(sc10) + __expf(sc11);
                usum[mi * 2]     += __expf(sc00 + aw0.x) + __expf(sc01 + aw0.y);
                usum[mi * 2 + 1] += __expf(sc10 + aw1.x) + __expf(sc11 + aw1.y);
            }
        }
        CPA_WAIT(0);
        __syncthreads();
    }

    #pragma unroll
    for (int sl = 0; sl < 4; sl++) {
        ssum[sl] += __shfl_xor_sync(~0u, ssum[sl], 1);
        ssum[sl] += __shfl_xor_sync(~0u, ssum[sl], 2);
        usum[sl] += __shfl_xor_sync(~0u, usum[sl], 1);
        usum[sl] += __shfl_xor_sync(~0u, usum[sl], 2);
    }
    if ((lane & 3) == 0) {
        #pragma unroll
        for (int sl = 0; sl < 4; sl++) {
            const int row = wm * 32 + (sl >> 1) * 16 + qr + 8 * (sl & 1);
            redS[wn * 128 + row] = ssum[sl];
            redU[wn * 128 + row] = usum[sl];
        }
    }
    __syncthreads();
    if (tid < 128) {
        float st = redS[tid] + redS[128 + tid] + redS[256 + tid] + redS[384 + tid];
        float ut = redU[tid] + redU[128 + tid] + redU[256 + tid] + redU[384 + tid];
        const int gi = bh * NN + q0 + tid;
        g_lse[gi] = __logf(st);
        g_isu[gi] = 1.0f / ut;
    }
}

// ============================================================================
// Pass 2 (R6-verbatim): logits + p, O = Phi.Vhi + Phi.Vlo + Plo.Vhi via smem P.
// ============================================================================
__global__ void __launch_bounds__(NT, 1) attn_av(const float* __restrict__ AW,
                                                 float* __restrict__ LOGOUT) {
    extern __shared__ char sm[];
    const uint32_t s0 = smem_u32(sm);
    const uint32_t sQH = s0, sQL = s0 + TILEB;
    const uint32_t sVH = s0 + 6 * TILEB, sVL = s0 + 7 * TILEB;
    const uint32_t pH = s0 + 8 * TILEB, pL = pH + PTILEB;

    const int tid = threadIdx.x, lane = tid & 31, wid = tid >> 5;
    const int wm = wid & 3, wn = wid >> 2;
    const int bh = blockIdx.y;
    const int q0 = blockIdx.x * 128;
    const int qr = lane >> 2, qc = (lane & 3) * 2;

    const size_t qbase = ((size_t)bh * NN + q0) * DD;
    const size_t kvbase = (size_t)bh * SS * DD;

    cpa_tile_pair(sQH, sQL, g_Qh, g_Ql, qbase, tid);
    cpa_tile_pair(s0 + 2 * TILEB, s0 + 3 * TILEB, g_Kh, g_Kl, kvbase, tid);
    CPA_COMMIT(); CPA_WAIT(0);
    __syncthreads();

    float lse_r[4], isu_r[4];
    #pragma unroll
    for (int sl = 0; sl < 4; sl++) {
        const int row = q0 + wm * 32 + (sl >> 1) * 16 + qr + 8 * (sl & 1);
        lse_r[sl] = g_lse[bh * NN + row];
        isu_r[sl] = g_isu[bh * NN + row];
    }

    float c2[2][2][4] = {};
    int buf = 0;

    for (int sc = 0; sc < 8; sc++) {
        cpa_tile_pair(sVH, sVL, g_Vh, g_Vl, kvbase + (size_t)sc * 128 * DD, tid);
        CPA_COMMIT();
        if (sc < 7) {
            cpa_tile_pair(s0 + (2 + 2 * (buf ^ 1)) * TILEB, s0 + (3 + 2 * (buf ^ 1)) * TILEB,
                          g_Kh, g_Kl, kvbase + (size_t)(sc + 1) * 128 * DD, tid);
            CPA_COMMIT();
        }
        const uint32_t kH = s0 + (2 + 2 * buf) * TILEB, kL = kH + TILEB;

        float c[2][4][4] = {};
        #pragma unroll
        for (int ks = 0; ks < 4; ks++) {
            uint32_t ah[2][4], al[2][4], bh2[4][2], bl2[4][2];
            #pragma unroll
            for (int mi = 0; mi < 2; mi++) {
                uint32_t off = ((wm * 32 + mi * 16 + (lane & 15)) * LDT + ks * 16 + (lane >> 4) * 8) * 2;
                ldsm_x4(ah[mi], sQH + off);
                ldsm_x4(al[mi], sQL + off);
            }
            #pragma unroll
            for (int ni = 0; ni < 4; ni++) {
                uint32_t off = ((wn * 32 + ni * 8 + (lane & 7)) * LDT + ks * 16 + ((lane >> 3) & 1) * 8) * 2;
                ldsm_x2(bh2[ni], kH + off);
                ldsm_x2(bl2[ni], kL + off);
            }
            #pragma unroll
            for (int mi = 0; mi < 2; mi++)
                #pragma unroll
                for (int ni = 0; ni < 4; ni++) {
                    mma_bf16(c[mi][ni], ah[mi], bh2[ni]);
                    mma_bf16(c[mi][ni], ah[mi], bl2[ni]);
                    mma_bf16(c[mi][ni], al[mi], bh2[ni]);
                }
        }

        const int s0c = sc * 128;
        #pragma unroll
        for (int mi = 0; mi < 2; mi++) {
            const size_t rb = ((size_t)bh * NN + q0 + wm * 32 + mi * 16 + qr) * SS + s0c + wn * 32 + qc;
            const int prow0 = wm * 32 + mi * 16 + qr;
            #pragma unroll
            for (int ni = 0; ni < 4; ni++) {
                float2 aw0 = *(const float2*)(AW + rb + ni * 8);
                float2 aw1 = *(const float2*)(AW + rb + (size_t)8 * SS + ni * 8);
                float u00 = fmaf(c[mi][ni][0], SCALEF, aw0.x);
                float u01 = fmaf(c[mi][ni][1], SCALEF, aw0.y);
                float u10 = fmaf(c[mi][ni][2], SCALEF, aw1.x);
                float u11 = fmaf(c[mi][ni][3], SCALEF, aw1.y);
                const int sl0 = mi * 2, sl1 = mi * 2 + 1;
                *(float2*)(LOGOUT + rb + ni * 8) = make_float2(u00 - lse_r[sl0], u01 - lse_r[sl0]);
                *(float2*)(LOGOUT + rb + (size_t)8 * SS + ni * 8) = make_float2(u10 - lse_r[sl1], u11 - lse_r[sl1]);
                float p00 = __expf(u00) * isu_r[sl0], p01 = __expf(u01) * isu_r[sl0];
                float p10 = __expf(u10) * isu_r[sl1], p11 = __expf(u11) * isu_r[sl1];
                const int pcol = wn * 32 + ni * 8 + qc;
                *(uint32_t*)(sm + (pH - s0) + (prow0 * LDP + pcol) * 2)       = packbf(p00, p01);
                *(uint32_t*)(sm + (pH - s0) + ((prow0 + 8) * LDP + pcol) * 2) = packbf(p10, p11);
                *(uint32_t*)(sm + (pL - s0) + (prow0 * LDP + pcol) * 2)       = packbf(bflo(p00), bflo(p01));
                *(uint32_t*)(sm + (pL - s0) + ((prow0 + 8) * LDP + pcol) * 2) = packbf(bflo(p10), bflo(p11));
            }
        }
        if (sc < 7) { CPA_WAIT(1); } else { CPA_WAIT(0); }
        __syncthreads();

        #pragma unroll
        for (int ksp = 0; ksp < 8; ksp++) {
            uint32_t pa[2][4], pe[2][4], vh[2][2], vl[2][2];
            #pragma unroll
            for (int mi = 0; mi < 2; mi++) {
                uint32_t off = ((wm * 32 + mi * 16 + (lane & 15)) * LDP + ksp * 16 + (lane >> 4) * 8) * 2;
                ldsm_x4(pa[mi], pH + off);
                ldsm_x4(pe[mi], pL + off);
            }
            #pragma unroll
            for (int nj = 0; nj < 2; nj++) {
                uint32_t off = ((ksp * 16 + (lane & 15)) * LDT + wn * 16 + nj * 8) * 2;
                ldsm_x2t(vh[nj], sVH + off);
                ldsm_x2t(vl[nj], sVL + off);
            }
            #pragma unroll
            for (int mi = 0; mi < 2; mi++)
                #pragma unroll
                for (int nj = 0; nj < 2; nj++) {
                    mma_bf16(c2[mi][nj], pa[mi], vh[nj]);
                    mma_bf16(c2[mi][nj], pa[mi], vl[nj]);
                    mma_bf16(c2[mi][nj], pe[mi], vh[nj]);
                }
        }
        CPA_WAIT(0);
        __syncthreads();
        buf ^= 1;
    }

    const int b = bh / HH, h = bh % HH;
    #pragma unroll
    for (int mi = 0; mi < 2; mi++)
        #pragma unroll
        for (int nj = 0; nj < 2; nj++) {
            const int row = q0 + wm * 32 + mi * 16 + qr;
            const int col = h * DD + wn * 16 + nj * 8 + qc;
            const size_t o0 = (size_t)(b * NN + row) * CC + col;
            const size_t o1 = (size_t)(b * NN + row + 8) * CC + col;
            float x0 = c2[mi][nj][0], x1 = c2[mi][nj][1];
            float x2 = c2[mi][nj][2], x3 = c2[mi][nj][3];
            *(uint32_t*)(g_AOh + o0) = packbf(x0, x1);
            *(uint32_t*)(g_AOh + o1) = packbf(x2, x3);
            *(uint32_t*)(g_AOl + o0) = packbf(bflo(x0), bflo(x1));
            *(uint32_t*)(g_AOl + o1) = packbf(bflo(x2), bflo(x3));
        }
}

// ============================================================================
extern "C" void kernel_launch(void* const* d_in, const int* in_sizes, int n_in,
                              void* d_out, int out_size) {
    const float* query = (const float*)d_in[0];
    const float* key_  = (const float*)d_in[1];
    const float* value = (const float*)d_in[2];
    const float* aw    = (const float*)d_in[3];
    const float* Wq    = (const float*)d_in[4];
    const float* Wk    = (const float*)d_in[5];
    const float* Wv    = (const float*)d_in[6];
    const float* Wo    = (const float*)d_in[7];
    const float* bo    = (const float*)d_in[8];

    float* out    = (float*)d_out;                       // [B,N,C]
    float* logout = out + (size_t)BB * NN * CC;          // [B,H,N,S]

    const int smem_gemm  = 8 * TILEB;                    // 147456
    const int smem_stats = 6 * TILEB + 2 * 4 * 128 * 4;  // 114688
    const int smem_av    = 8 * TILEB + 2 * PTILEB;       // 217088
    cudaFuncSetAttribute(tc_gemm_qkv, cudaFuncAttributeMaxDynamicSharedMemorySize, smem_gemm);
    cudaFuncSetAttribute(tc_gemm_out, cudaFuncAttributeMaxDynamicSharedMemorySize, smem_gemm);
    cudaFuncSetAttribute(attn_stats,  cudaFuncAttributeMaxDynamicSharedMemorySize, smem_stats);
    cudaFuncSetAttribute(attn_av,     cudaFuncAttributeMaxDynamicSharedMemorySize, smem_av);

    const int nX4 = (BB * NN * CC) / 4;
    const int nW4 = (CC * CC) / 4;
    dim3 gsx((nX4 + 255) / 256, 1, 3);
    dim3 gsw((nW4 + 255) / 256, 1, 4);
    dim3 gqkv(CC / 128, (BB * NN) / 128, 3);   // 6 x 64 x 3
    dim3 gp(CC / 128, (BB * NN) / 128);        // 6 x 64
    dim3 ga(NN / 128, BB * HH);                // 8 x 96

    split_x3<<<gsx, 256>>>(query, key_, value, nX4);
    split_w4<<<gsw, 256>>>(Wq, Wk, Wv, Wo, nW4);
    tc_gemm_qkv<<<gqkv, NT, smem_gemm>>>();
    attn_stats<<<ga, NT, smem_stats>>>(aw);
    attn_av<<<ga, NT, smem_av>>>(aw, logout);
    tc_gemm_out<<<gp, NT, smem_gemm>>>(bo, out);
}